// round 1
// baseline (speedup 1.0000x reference)
#include <cuda_runtime.h>
#include <cstdint>

typedef unsigned long long ull;

#define TT 512
#define BB 32
#define DD 1280
#define TBD (TT*BB*DD)   // 20971520
#define RNC 128          // recurrence CTAs (<=148 SMs -> co-resident, spin-barrier safe)
#define JPC 10           // output columns per recurrence CTA (128*10 = 1280)
#define RTPB 160         // 5 warps, warp w handles column pair (2w, 2w+1)

// -------- device scratch (no allocations allowed) --------
__device__ float g_xp[TBD];                 // x @ Wx^T + b, layout [t][b][e]
__device__ float g_h[2][BB*DD];             // h double buffer, layout [(k>>2)*128 + b*4 + (k&3)]
__device__ volatile int g_flags[RNC];       // distributed barrier flags (monotonic per launch)
__device__ float g_hlast_dummy[BB*DD];      // fallback if out buffer has no h_last region

// -------- packed f32x2 helpers (Blackwell FFMA2 path) --------
__device__ __forceinline__ ull pack2(float lo, float hi){
  ull r; asm("mov.b64 %0, {%1, %2};" : "=l"(r) : "f"(lo), "f"(hi)); return r;
}
__device__ __forceinline__ float2 unpack2(ull v){
  float2 r; asm("mov.b64 {%0, %1}, %2;" : "=f"(r.x), "=f"(r.y) : "l"(v)); return r;
}
__device__ __forceinline__ void ffma2(ull& d, ull a, ull b){
  asm("fma.rn.f32x2 %0, %1, %2, %0;" : "+l"(d) : "l"(a), "l"(b));
}

// ======================================================================
// Kernel 1: x_proj[m][n] = sum_k X[m][k] * Wx[n][k] + bias[n]
// M = T*B = 16384, N = K = 1280. 128x128 tile, BK=16, 256 threads, 8x8/thread.
// ======================================================================
#define BK 16
#define LDA 132

__global__ __launch_bounds__(256) void gemm_xproj(
    const float* __restrict__ X, const float* __restrict__ W,
    const float* __restrict__ bias)
{
  __shared__ float As[BK][LDA];   // As[k][m]
  __shared__ float Bs[BK][LDA];   // Bs[k][n]
  const int tid = threadIdx.x;
  const int m0 = blockIdx.x * 128;
  const int n0 = blockIdx.y * 128;
  const int tn = tid & 15, tm = tid >> 4;   // n fast across lanes -> coalesced C writes

  ull acc[8][4];
  #pragma unroll
  for (int i = 0; i < 8; i++)
    #pragma unroll
    for (int j = 0; j < 4; j++) acc[i][j] = 0ull;

  for (int k0 = 0; k0 < DD; k0 += BK) {
    __syncthreads();
    #pragma unroll
    for (int it = 0; it < 2; ++it) {
      int s = tid + it * 256;          // 512 float4 slots: 128 rows x 4
      int row = s >> 2, c4 = (s & 3) * 4;
      float4 va = *(const float4*)&X[(size_t)(m0 + row) * DD + k0 + c4];
      As[c4+0][row] = va.x; As[c4+1][row] = va.y;
      As[c4+2][row] = va.z; As[c4+3][row] = va.w;
      float4 vb = *(const float4*)&W[(size_t)(n0 + row) * DD + k0 + c4];
      Bs[c4+0][row] = vb.x; Bs[c4+1][row] = vb.y;
      Bs[c4+2][row] = vb.z; Bs[c4+3][row] = vb.w;
    }
    __syncthreads();
    #pragma unroll
    for (int k = 0; k < BK; ++k) {
      float4 a0 = *(const float4*)&As[k][tm*4];
      float4 a1 = *(const float4*)&As[k][tm*4 + 64];
      ulonglong2 bA = *(const ulonglong2*)&Bs[k][tn*4];       // pairs (n,n+1),(n+2,n+3)
      ulonglong2 bB = *(const ulonglong2*)&Bs[k][tn*4 + 64];
      float av[8] = {a0.x, a0.y, a0.z, a0.w, a1.x, a1.y, a1.z, a1.w};
      #pragma unroll
      for (int i = 0; i < 8; i++) {
        ull ad = pack2(av[i], av[i]);
        ffma2(acc[i][0], ad, bA.x); ffma2(acc[i][1], ad, bA.y);
        ffma2(acc[i][2], ad, bB.x); ffma2(acc[i][3], ad, bB.y);
      }
    }
  }

  float4 bias_a = *(const float4*)&bias[n0 + tn*4];
  float4 bias_b = *(const float4*)&bias[n0 + tn*4 + 64];
  #pragma unroll
  for (int i = 0; i < 8; i++) {
    int m = m0 + tm*4 + (i < 4 ? i : 60 + i);
    float2 p0 = unpack2(acc[i][0]), p1 = unpack2(acc[i][1]);
    float2 p2 = unpack2(acc[i][2]), p3 = unpack2(acc[i][3]);
    float4 c0 = make_float4(p0.x + bias_a.x, p0.y + bias_a.y,
                            p1.x + bias_a.z, p1.y + bias_a.w);
    float4 c1 = make_float4(p2.x + bias_b.x, p2.y + bias_b.y,
                            p3.x + bias_b.z, p3.y + bias_b.w);
    *(float4*)&g_xp[(size_t)m * DD + n0 + tn*4]      = c0;
    *(float4*)&g_xp[(size_t)m * DD + n0 + tn*4 + 64] = c1;
  }
}

// ======================================================================
// Kernel 0: reset barrier flags + transpose h0 into interleaved layout
// ======================================================================
__global__ void init_state(const float* __restrict__ h0)
{
  int idx = blockIdx.x * blockDim.x + threadIdx.x;
  int stride = gridDim.x * blockDim.x;
  if (idx < RNC) g_flags[idx] = 0;
  for (int i = idx; i < BB * DD; i += stride) {
    int b = i / DD, k = i % DD;
    g_h[0][(k >> 2) * 128 + b * 4 + (k & 3)] = h0[i];
  }
}

// ======================================================================
// Kernel 2: persistent recurrence. 128 CTAs x 160 threads.
// lane = batch b, warp w owns columns (j0+2w, j0+2w+1).
// Wh slice (10 rows = 50KB) lives in smem for the whole sequence.
// ======================================================================
__global__ __launch_bounds__(RTPB) void recurrence(
    const float* __restrict__ zseq, const float* __restrict__ Wh,
    float* __restrict__ out, float* __restrict__ hlast)
{
  extern __shared__ float ws[];          // [JPC][DD]
  const int tid = threadIdx.x, bid = blockIdx.x;
  const int j0 = bid * JPC;

  for (int i = tid * 4; i < JPC * DD; i += RTPB * 4)
    *(float4*)&ws[i] = *(const float4*)&Wh[(size_t)j0 * DD + i];
  __syncthreads();

  const int lane = tid & 31, w = tid >> 5;
  const int ja = j0 + 2 * w, jb = ja + 1;
  const float* wva = ws + (2 * w) * DD;
  const float* wvb = wva + DD;

  for (int t = 0; t < TT; ++t) {
    const float* hc = g_h[t & 1];
    float*       hn = g_h[(t & 1) ^ 1];

    ull a0 = 0, a1 = 0, b0 = 0, b1 = 0;
    #pragma unroll 1
    for (int k = 0; k < DD; k += 32) {
      #pragma unroll
      for (int kk = 0; kk < 32; kk += 8) {
        int kb = k + kk;
        // h: coalesced LDG.128 per lane, 4 consecutive k for batch=lane
        ulonglong2 h01 = *(const ulonglong2*)&hc[(kb >> 2) * 128 + lane * 4];
        ulonglong2 h23 = *(const ulonglong2*)&hc[((kb >> 2) + 1) * 128 + lane * 4];
        // w: broadcast LDS.128 (uniform across lanes -> cheap on crossbar)
        ulonglong2 wa01 = *(const ulonglong2*)(wva + kb);
        ulonglong2 wa23 = *(const ulonglong2*)(wva + kb + 4);
        ulonglong2 wb01 = *(const ulonglong2*)(wvb + kb);
        ulonglong2 wb23 = *(const ulonglong2*)(wvb + kb + 4);
        ffma2(a0, h01.x, wa01.x); ffma2(a1, h01.y, wa01.y);
        ffma2(a0, h23.x, wa23.x); ffma2(a1, h23.y, wa23.y);
        ffma2(b0, h01.x, wb01.x); ffma2(b1, h01.y, wb01.y);
        ffma2(b0, h23.x, wb23.x); ffma2(b1, h23.y, wb23.y);
      }
    }
    float2 fa0 = unpack2(a0), fa1 = unpack2(a1);
    float2 fb0 = unpack2(b0), fb1 = unpack2(b1);
    float sa = (fa0.x + fa0.y) + (fa1.x + fa1.y);
    float sb = (fb0.x + fb0.y) + (fb1.x + fb1.y);

    size_t base = (size_t)t * (BB * DD) + (size_t)lane * DD;
    float preA = g_xp[base + ja] + sa;
    float preB = g_xp[base + jb] + sb;
    float hA = tanhf(preA), hB = tanhf(preB);
    float zA = zseq[base + ja], zB = zseq[base + jb];
    float yA = hA * (zA / (1.0f + expf(-zA)));   // h * silu(z)
    float yB = hB * (zB / (1.0f + expf(-zB)));
    out[base + ja] = yA;
    out[base + jb] = yB;
    hn[(ja >> 2) * 128 + lane * 4 + (ja & 3)] = hA;
    hn[(jb >> 2) * 128 + lane * 4 + (jb & 3)] = hB;
    if (t == TT - 1) {
      hlast[(size_t)lane * DD + ja] = hA;
      hlast[(size_t)lane * DD + jb] = hB;
    }

    // ---- grid barrier: distributed flags, no contended atomics ----
    __syncthreads();                       // all CTA stores done & visible to tid0
    if (tid == 0) {
      __threadfence();                     // release (cumulative over CTA's stores)
      g_flags[bid] = t + 1;                // volatile store, bypasses L1
    }
    if (tid < RNC) {
      while (g_flags[tid] < t + 1) { }     // volatile spin
    }
    __syncthreads();
    __threadfence();                       // acquire + CCTL.IVALL: fresh h next step
  }
}

// ======================================================================
extern "C" void kernel_launch(void* const* d_in, const int* in_sizes, int n_in,
                              void* d_out, int out_size)
{
  const float* x    = (const float*)d_in[0];   // [T,B,D]
  const float* z    = (const float*)d_in[1];   // [T,B,D]
  const float* h0   = (const float*)d_in[2];   // [B,D]
  const float* Wx   = (const float*)d_in[3];   // [D,D]
  const float* Wh   = (const float*)d_in[4];   // [D,D]
  const float* bias = (const float*)d_in[5];   // [D]

  float* out = (float*)d_out;
  void* dummy = nullptr;
  cudaGetSymbolAddress(&dummy, g_hlast_dummy);
  float* hlast = (out_size >= (int)(TBD + BB * DD)) ? (out + TBD) : (float*)dummy;

  cudaFuncSetAttribute(recurrence, cudaFuncAttributeMaxDynamicSharedMemorySize,
                       JPC * DD * (int)sizeof(float));

  init_state<<<40, 256>>>(h0);
  gemm_xproj<<<dim3(128, 10), 256>>>(x, Wx, bias);
  recurrence<<<RNC, RTPB, JPC * DD * sizeof(float)>>>(z, Wh, out, hlast);
}

// round 2
// speedup vs baseline: 3.8153x; 3.8153x over previous
#include <cuda_runtime.h>
#include <cstdint>

typedef unsigned long long ull;

#define TT 512
#define BB 32
#define DD 1280
#define TBD (TT*BB*DD)   // 20971520
#define RNC 128          // recurrence CTAs (<=148 SMs -> co-resident, spin-barrier safe)
#define JPC 10           // output columns per recurrence CTA
#define RTPB 256         // 8 warps, balanced 2 per SMSP
#define NW 8
#define QSPAN 40         // k-quads per warp (40*4 = 160 k, 8*160 = 1280)

// -------- device scratch (no allocations allowed) --------
__device__ float g_xp[TBD];                 // x @ Wx^T + b, layout [t][b][e]
__device__ float g_h[2][BB*DD];             // h double buffer: [(k>>2)*128 + b*4 + (k&3)]
__device__ unsigned g_count;                // barrier arrival counter (monotonic per launch)
__device__ unsigned g_go[RNC*32];           // per-CTA go flags, 128B apart (own L2 sector each)
__device__ float g_hlast_dummy[BB*DD];

// -------- packed f32x2 helpers --------
__device__ __forceinline__ ull pack2(float lo, float hi){
  ull r; asm("mov.b64 %0, {%1, %2};" : "=l"(r) : "f"(lo), "f"(hi)); return r;
}
__device__ __forceinline__ float2 unpack2(ull v){
  float2 r; asm("mov.b64 {%0, %1}, %2;" : "=f"(r.x), "=f"(r.y) : "l"(v)); return r;
}
__device__ __forceinline__ void ffma2(ull& d, ull a, ull b){
  asm("fma.rn.f32x2 %0, %1, %2, %0;" : "+l"(d) : "l"(a), "l"(b));
}
__device__ __forceinline__ void ld_cg_v2u64(const void* p, ull& a, ull& b){
  asm volatile("ld.global.cg.v2.u64 {%0, %1}, [%2];" : "=l"(a), "=l"(b) : "l"(p));
}

// ======================================================================
// Kernel 1: x_proj[m][n] = sum_k X[m][k] * Wx[n][k] + bias[n]
// ======================================================================
#define BK 16
#define LDA 132

__global__ __launch_bounds__(256) void gemm_xproj(
    const float* __restrict__ X, const float* __restrict__ W,
    const float* __restrict__ bias)
{
  __shared__ float As[BK][LDA];
  __shared__ float Bs[BK][LDA];
  const int tid = threadIdx.x;
  const int m0 = blockIdx.x * 128;
  const int n0 = blockIdx.y * 128;
  const int tn = tid & 15, tm = tid >> 4;

  ull acc[8][4];
  #pragma unroll
  for (int i = 0; i < 8; i++)
    #pragma unroll
    for (int j = 0; j < 4; j++) acc[i][j] = 0ull;

  for (int k0 = 0; k0 < DD; k0 += BK) {
    __syncthreads();
    #pragma unroll
    for (int it = 0; it < 2; ++it) {
      int s = tid + it * 256;
      int row = s >> 2, c4 = (s & 3) * 4;
      float4 va = *(const float4*)&X[(size_t)(m0 + row) * DD + k0 + c4];
      As[c4+0][row] = va.x; As[c4+1][row] = va.y;
      As[c4+2][row] = va.z; As[c4+3][row] = va.w;
      float4 vb = *(const float4*)&W[(size_t)(n0 + row) * DD + k0 + c4];
      Bs[c4+0][row] = vb.x; Bs[c4+1][row] = vb.y;
      Bs[c4+2][row] = vb.z; Bs[c4+3][row] = vb.w;
    }
    __syncthreads();
    #pragma unroll
    for (int k = 0; k < BK; ++k) {
      float4 a0 = *(const float4*)&As[k][tm*4];
      float4 a1 = *(const float4*)&As[k][tm*4 + 64];
      ulonglong2 bA = *(const ulonglong2*)&Bs[k][tn*4];
      ulonglong2 bB = *(const ulonglong2*)&Bs[k][tn*4 + 64];
      float av[8] = {a0.x, a0.y, a0.z, a0.w, a1.x, a1.y, a1.z, a1.w};
      #pragma unroll
      for (int i = 0; i < 8; i++) {
        ull ad = pack2(av[i], av[i]);
        ffma2(acc[i][0], ad, bA.x); ffma2(acc[i][1], ad, bA.y);
        ffma2(acc[i][2], ad, bB.x); ffma2(acc[i][3], ad, bB.y);
      }
    }
  }

  float4 bias_a = *(const float4*)&bias[n0 + tn*4];
  float4 bias_b = *(const float4*)&bias[n0 + tn*4 + 64];
  #pragma unroll
  for (int i = 0; i < 8; i++) {
    int m = m0 + tm*4 + (i < 4 ? i : 60 + i);
    float2 p0 = unpack2(acc[i][0]), p1 = unpack2(acc[i][1]);
    float2 p2 = unpack2(acc[i][2]), p3 = unpack2(acc[i][3]);
    float4 c0 = make_float4(p0.x + bias_a.x, p0.y + bias_a.y,
                            p1.x + bias_a.z, p1.y + bias_a.w);
    float4 c1 = make_float4(p2.x + bias_b.x, p2.y + bias_b.y,
                            p3.x + bias_b.z, p3.y + bias_b.w);
    *(float4*)&g_xp[(size_t)m * DD + n0 + tn*4]      = c0;
    *(float4*)&g_xp[(size_t)m * DD + n0 + tn*4 + 64] = c1;
  }
}

// ======================================================================
// Kernel 0: reset barrier state + transpose h0 into interleaved layout
// ======================================================================
__global__ void init_state(const float* __restrict__ h0)
{
  int idx = blockIdx.x * blockDim.x + threadIdx.x;
  int stride = gridDim.x * blockDim.x;
  if (idx == 0) g_count = 0;
  if (idx < RNC * 32) g_go[idx] = 0;
  for (int i = idx; i < BB * DD; i += stride) {
    int b = i / DD, k = i % DD;
    g_h[0][(k >> 2) * 128 + b * 4 + (k & 3)] = h0[i];
  }
}

// ======================================================================
// Kernel 2: persistent recurrence. 128 CTAs x 256 threads (8 warps).
// k-split across warps (C=10 column amortization of every h load);
// cross-warp partial sums reduced through smem; low-contention barrier.
// ======================================================================
__global__ __launch_bounds__(RTPB, 1) void recurrence(
    const float* __restrict__ zseq, const float* __restrict__ Wh,
    float* __restrict__ out, float* __restrict__ hlast)
{
  extern __shared__ float sm[];
  float* ws   = sm;               // [kq][j][4k] : JPC*DD floats (51.2 KB)
  float* redb = sm + JPC * DD;    // [wid][lane][12] : 8*384 floats (12.3 KB)

  const int tid = threadIdx.x, bid = blockIdx.x;
  const int lane = tid & 31, wid = tid >> 5;
  const int j0 = bid * JPC;

  // Load Wh slice into smem, layout ws[(kq*JPC + j)*4 + kk] = Wh[j0+j][4kq+kk]
  {
    float4* ws4 = (float4*)ws;
    const float4* W4 = (const float4*)Wh;
    for (int i = tid; i < JPC * (DD/4); i += RTPB) {
      int j = i / (DD/4), kq = i % (DD/4);
      ws4[kq * JPC + j] = W4[(size_t)(j0 + j) * (DD/4) + kq];
    }
  }

  // Epilogue task mapping: task = b*JPC + jj (320 tasks over 256 threads)
  const int task1 = tid;
  const int b1 = task1 / JPC, jj1 = task1 % JPC;
  const int o1  = b1 * DD + j0 + jj1;
  const int ha1 = ((j0 + jj1) >> 2) * 128 + b1 * 4 + ((j0 + jj1) & 3);
  const bool has2 = (tid < JPC * BB - RTPB);   // first 64 threads take a 2nd task
  const int task2 = tid + RTPB;
  const int b2 = task2 / JPC, jj2 = task2 % JPC;
  const int o2  = b2 * DD + j0 + jj2;
  const int ha2 = ((j0 + jj2) >> 2) * 128 + b2 * 4 + ((j0 + jj2) & 3);

  __syncthreads();

  const int kq0 = wid * QSPAN;     // this warp's k-quad range

  // prefetch step-0 gate inputs into registers
  size_t base = 0;
  float xp1 = __ldcs(&g_xp[o1]);
  float z1  = __ldcs(&zseq[o1]);
  float xp2 = has2 ? __ldcs(&g_xp[o2]) : 0.f;
  float z2  = has2 ? __ldcs(&zseq[o2]) : 0.f;

  for (int t = 0; t < TT; ++t) {
    const float* hc = g_h[t & 1];
    float*       hn = g_h[(t & 1) ^ 1];
    float sz1 = z1 / (1.0f + __expf(-z1));                 // silu off critical path
    float sz2 = has2 ? (z2 / (1.0f + __expf(-z2))) : 0.f;

    // ---- partial dot products: lane = batch, 10 columns, k in [kq0*4, kq0*4+160) ----
    ull acc[JPC];
    #pragma unroll
    for (int j = 0; j < JPC; ++j) acc[j] = 0ull;

    const char* hp = (const char*)(hc + (size_t)kq0 * 128 + lane * 4);
    ull h0c, h1c;
    ld_cg_v2u64(hp, h0c, h1c);                             // h[b][4k], L2-only
    #pragma unroll 2
    for (int q = 0; q < QSPAN; ++q) {
      ull h0 = h0c, h1 = h1c;
      if (q + 1 < QSPAN) ld_cg_v2u64(hp + (size_t)(q + 1) * 512, h0c, h1c);
      const ulonglong2* wq = (const ulonglong2*)(ws + (size_t)(kq0 + q) * (JPC * 4));
      #pragma unroll
      for (int j = 0; j < JPC; ++j) {
        ulonglong2 wv = wq[j];       // broadcast LDS.128: w[j][4k]
        ffma2(acc[j], h0, wv.x);
        ffma2(acc[j], h1, wv.y);
      }
    }

    // ---- stage partials: redb[wid][lane][j] ----
    {
      float s[JPC];
      #pragma unroll
      for (int j = 0; j < JPC; ++j) { float2 p = unpack2(acc[j]); s[j] = p.x + p.y; }
      float* rp = redb + wid * 384 + lane * 12;
      *(float4*)(rp + 0) = make_float4(s[0], s[1], s[2], s[3]);
      *(float4*)(rp + 4) = make_float4(s[4], s[5], s[6], s[7]);
      *(float2*)(rp + 8) = make_float2(s[8], s[9]);
    }
    __syncthreads();   // A: partials visible

    // ---- epilogue: reduce 8 partials, tanh, gate, store ----
    {
      float s = 0.f;
      #pragma unroll
      for (int w = 0; w < NW; ++w) s += redb[w * 384 + b1 * 12 + jj1];
      float h = tanhf(xp1 + s);
      out[base + o1] = h * sz1;
      hn[ha1] = h;
      if (t == TT - 1) hlast[o1] = h;
    }
    if (has2) {
      float s = 0.f;
      #pragma unroll
      for (int w = 0; w < NW; ++w) s += redb[w * 384 + b2 * 12 + jj2];
      float h = tanhf(xp2 + s);
      out[base + o2] = h * sz2;
      hn[ha2] = h;
      if (t == TT - 1) hlast[o2] = h;
    }
    __syncthreads();   // B: all hn stores issued, redb reads done

    // ---- arrive: one REDG per CTA (release, cumulative over CTA stores) ----
    if (tid == 0)
      asm volatile("red.release.gpu.global.add.u32 [%0], 1;" :: "l"(&g_count) : "memory");

    // prefetch next step's gate inputs (overlaps barrier wait)
    base += (size_t)BB * DD;
    if (t + 1 < TT) {
      xp1 = __ldcs(&g_xp[base + o1]);
      z1  = __ldcs(&zseq[base + o1]);
      if (has2) { xp2 = __ldcs(&g_xp[base + o2]); z2 = __ldcs(&zseq[base + o2]); }
    }

    // ---- CTA0 aggregates and fans out go flags (1 poller on the counter) ----
    if (bid == 0) {
      if (tid == 0) {
        unsigned target = (unsigned)RNC * (unsigned)(t + 1), v;
        while (true) {
          asm volatile("ld.acquire.gpu.global.u32 %0, [%1];" : "=r"(v) : "l"(&g_count));
          if (v >= target) break;
          __nanosleep(32);
        }
      }
      __syncthreads();   // D (CTA0 only)
      if (tid < RNC)
        asm volatile("st.release.gpu.global.u32 [%0], %1;"
                     :: "l"(&g_go[tid * 32]), "r"(t + 1) : "memory");
    }
    // ---- every CTA: tid0 polls its own go sector (128 pollers, disjoint sectors) ----
    if (tid == 0) {
      unsigned v;
      while (true) {
        asm volatile("ld.acquire.gpu.global.u32 %0, [%1];" : "=r"(v) : "l"(&g_go[bid * 32]));
        if (v >= (unsigned)(t + 1)) break;
        __nanosleep(32);
      }
    }
    __syncthreads();   // C: release barrier; h loads are .cg (L2) so no L1 flush needed
  }
}

// ======================================================================
extern "C" void kernel_launch(void* const* d_in, const int* in_sizes, int n_in,
                              void* d_out, int out_size)
{
  const float* x    = (const float*)d_in[0];   // [T,B,D]
  const float* z    = (const float*)d_in[1];   // [T,B,D]
  const float* h0   = (const float*)d_in[2];   // [B,D]
  const float* Wx   = (const float*)d_in[3];   // [D,D]
  const float* Wh   = (const float*)d_in[4];   // [D,D]
  const float* bias = (const float*)d_in[5];   // [D]

  float* out = (float*)d_out;
  void* dummy = nullptr;
  cudaGetSymbolAddress(&dummy, g_hlast_dummy);
  float* hlast = (out_size >= (int)(TBD + BB * DD)) ? (out + TBD) : (float*)dummy;

  const int rec_smem = (JPC * DD + NW * 384) * (int)sizeof(float);
  cudaFuncSetAttribute(recurrence, cudaFuncAttributeMaxDynamicSharedMemorySize, rec_smem);

  init_state<<<40, 256>>>(h0);
  gemm_xproj<<<dim3(128, 10), 256>>>(x, Wx, bias);
  recurrence<<<RNC, RTPB, rec_smem>>>(z, Wh, out, hlast);
}

// round 3
// speedup vs baseline: 5.2210x; 1.3684x over previous
#include <cuda_runtime.h>
#include <cstdint>

typedef unsigned long long ull;

#define TT 512
#define BB 32
#define DD 1280
#define TBD (TT*BB*DD)   // 20971520
#define RNC 128          // recurrence CTAs (co-resident: 128 <= 148 SMs, occ 1)
#define JPC 10           // output columns per recurrence CTA
#define RTPB 256         // 8 warps, balanced 2 per SMSP
#define NW 8
#define QSPAN 40         // k-quads per warp (40*4 = 160 k, 8*160 = 1280)

// -------- device scratch (no allocations allowed) --------
__device__ float g_xp[TBD];                 // x @ Wx^T + b, layout [t][b][e]
__device__ float g_h[2][BB*DD];             // h double buffer: [(k>>2)*128 + b*4 + (k&3)]
__device__ unsigned g_flag[RNC];            // producer flags: flag[c]=v  <=>  h_v cols of c written
__device__ float g_hlast_dummy[BB*DD];

// -------- packed f32x2 + memory helpers --------
__device__ __forceinline__ ull pack2(float lo, float hi){
  ull r; asm("mov.b64 %0, {%1, %2};" : "=l"(r) : "f"(lo), "f"(hi)); return r;
}
__device__ __forceinline__ float2 unpack2(ull v){
  float2 r; asm("mov.b64 {%0, %1}, %2;" : "=f"(r.x), "=f"(r.y) : "l"(v)); return r;
}
__device__ __forceinline__ void ffma2(ull& d, ull a, ull b){
  asm("fma.rn.f32x2 %0, %1, %2, %0;" : "+l"(d) : "l"(a), "l"(b));
}
__device__ __forceinline__ void ld_cg_v2u64(const void* p, ull& a, ull& b){
  asm volatile("ld.global.cg.v2.u64 {%0, %1}, [%2];" : "=l"(a), "=l"(b) : "l"(p));
}
__device__ __forceinline__ void st_cg_f32(float* p, float v){
  asm volatile("st.global.cg.f32 [%0], %1;" :: "l"(p), "f"(v) : "memory");
}
__device__ __forceinline__ unsigned ld_acq(const unsigned* p){
  unsigned v; asm volatile("ld.acquire.gpu.global.u32 %0, [%1];" : "=r"(v) : "l"(p)); return v;
}
__device__ __forceinline__ void st_rel(unsigned* p, unsigned v){
  asm volatile("st.release.gpu.global.u32 [%0], %1;" :: "l"(p), "r"(v) : "memory");
}

// ======================================================================
// Kernel 1: x_proj[m][n] = sum_k X[m][k] * Wx[n][k] + bias[n]
// 128x128 tile, BK=16, 256 threads, 8x8/thread, double-buffered smem.
// ======================================================================
#define BK 16
#define LDA 132
#define KTILES (DD/BK)   // 80

__global__ __launch_bounds__(256) void gemm_xproj(
    const float* __restrict__ X, const float* __restrict__ W,
    const float* __restrict__ bias)
{
  __shared__ float As[2][BK][LDA];
  __shared__ float Bs[2][BK][LDA];
  const int tid = threadIdx.x;
  const int m0 = blockIdx.x * 128;
  const int n0 = blockIdx.y * 128;
  const int tn = tid & 15, tm = tid >> 4;
  // loader indices: 512 float4 slots per array, 2 per thread
  const int r0 = (tid)       >> 2, c0 = ((tid) & 3) * 4;
  const int r1 = (tid + 256) >> 2, c1 = ((tid + 256) & 3) * 4;

  ull acc[8][4];
  #pragma unroll
  for (int i = 0; i < 8; i++)
    #pragma unroll
    for (int j = 0; j < 4; j++) acc[i][j] = 0ull;

  // prologue: tile 0 -> buf 0
  {
    float4 va0 = *(const float4*)&X[(size_t)(m0 + r0) * DD + c0];
    float4 va1 = *(const float4*)&X[(size_t)(m0 + r1) * DD + c1];
    float4 vb0 = *(const float4*)&W[(size_t)(n0 + r0) * DD + c0];
    float4 vb1 = *(const float4*)&W[(size_t)(n0 + r1) * DD + c1];
    As[0][c0+0][r0]=va0.x; As[0][c0+1][r0]=va0.y; As[0][c0+2][r0]=va0.z; As[0][c0+3][r0]=va0.w;
    As[0][c1+0][r1]=va1.x; As[0][c1+1][r1]=va1.y; As[0][c1+2][r1]=va1.z; As[0][c1+3][r1]=va1.w;
    Bs[0][c0+0][r0]=vb0.x; Bs[0][c0+1][r0]=vb0.y; Bs[0][c0+2][r0]=vb0.z; Bs[0][c0+3][r0]=vb0.w;
    Bs[0][c1+0][r1]=vb1.x; Bs[0][c1+1][r1]=vb1.y; Bs[0][c1+2][r1]=vb1.z; Bs[0][c1+3][r1]=vb1.w;
  }
  __syncthreads();

  for (int kt = 0; kt < KTILES; ++kt) {
    const int cur = kt & 1, nxt = cur ^ 1;
    float4 va0, va1, vb0, vb1;
    const bool more = (kt + 1 < KTILES);
    if (more) {
      int kk = (kt + 1) * BK;
      va0 = *(const float4*)&X[(size_t)(m0 + r0) * DD + kk + c0];
      va1 = *(const float4*)&X[(size_t)(m0 + r1) * DD + kk + c1];
      vb0 = *(const float4*)&W[(size_t)(n0 + r0) * DD + kk + c0];
      vb1 = *(const float4*)&W[(size_t)(n0 + r1) * DD + kk + c1];
    }
    #pragma unroll
    for (int k = 0; k < BK; ++k) {
      float4 a0 = *(const float4*)&As[cur][k][tm*4];
      float4 a1 = *(const float4*)&As[cur][k][tm*4 + 64];
      ulonglong2 bA = *(const ulonglong2*)&Bs[cur][k][tn*4];
      ulonglong2 bB = *(const ulonglong2*)&Bs[cur][k][tn*4 + 64];
      float av[8] = {a0.x, a0.y, a0.z, a0.w, a1.x, a1.y, a1.z, a1.w};
      #pragma unroll
      for (int i = 0; i < 8; i++) {
        ull ad = pack2(av[i], av[i]);
        ffma2(acc[i][0], ad, bA.x); ffma2(acc[i][1], ad, bA.y);
        ffma2(acc[i][2], ad, bB.x); ffma2(acc[i][3], ad, bB.y);
      }
    }
    if (more) {
      As[nxt][c0+0][r0]=va0.x; As[nxt][c0+1][r0]=va0.y; As[nxt][c0+2][r0]=va0.z; As[nxt][c0+3][r0]=va0.w;
      As[nxt][c1+0][r1]=va1.x; As[nxt][c1+1][r1]=va1.y; As[nxt][c1+2][r1]=va1.z; As[nxt][c1+3][r1]=va1.w;
      Bs[nxt][c0+0][r0]=vb0.x; Bs[nxt][c0+1][r0]=vb0.y; Bs[nxt][c0+2][r0]=vb0.z; Bs[nxt][c0+3][r0]=vb0.w;
      Bs[nxt][c1+0][r1]=vb1.x; Bs[nxt][c1+1][r1]=vb1.y; Bs[nxt][c1+2][r1]=vb1.z; Bs[nxt][c1+3][r1]=vb1.w;
    }
    __syncthreads();
  }

  float4 bias_a = *(const float4*)&bias[n0 + tn*4];
  float4 bias_b = *(const float4*)&bias[n0 + tn*4 + 64];
  #pragma unroll
  for (int i = 0; i < 8; i++) {
    int m = m0 + tm*4 + (i < 4 ? i : 60 + i);
    float2 p0 = unpack2(acc[i][0]), p1 = unpack2(acc[i][1]);
    float2 p2 = unpack2(acc[i][2]), p3 = unpack2(acc[i][3]);
    float4 c0v = make_float4(p0.x + bias_a.x, p0.y + bias_a.y,
                             p1.x + bias_a.z, p1.y + bias_a.w);
    float4 c1v = make_float4(p2.x + bias_b.x, p2.y + bias_b.y,
                             p3.x + bias_b.z, p3.y + bias_b.w);
    *(float4*)&g_xp[(size_t)m * DD + n0 + tn*4]      = c0v;
    *(float4*)&g_xp[(size_t)m * DD + n0 + tn*4 + 64] = c1v;
  }
}

// ======================================================================
// Kernel 0: reset flags + transpose h0 into interleaved layout
// ======================================================================
__global__ void init_state(const float* __restrict__ h0)
{
  int idx = blockIdx.x * blockDim.x + threadIdx.x;
  int stride = gridDim.x * blockDim.x;
  if (idx < RNC) g_flag[idx] = 0;
  for (int i = idx; i < BB * DD; i += stride) {
    int b = i / DD, k = i % DD;
    g_h[0][(k >> 2) * 128 + b * 4 + (k & 3)] = h0[i];
  }
}

// ======================================================================
// Kernel 2: persistent recurrence, dataflow-synced.
// Every CTA reads ALL producers each step => NBUF=2 provably safe:
// entering step t, all 8 warps observed flag[c] >= t for all c, which
// implies every CTA finished reading h_{t-1} (the buffer we overwrite).
// ======================================================================
__global__ __launch_bounds__(RTPB, 1) void recurrence(
    const float* __restrict__ zseq, const float* __restrict__ Wh,
    float* __restrict__ out, float* __restrict__ hlast)
{
  extern __shared__ float sm[];
  float* ws   = sm;               // [kq][j][4k] : JPC*DD floats (51.2 KB)
  float* redb = sm + JPC * DD;    // [wid][lane][12] : 8*384 floats (12.3 KB)

  const int tid = threadIdx.x, bid = blockIdx.x;
  const int lane = tid & 31, wid = tid >> 5;
  const int j0 = bid * JPC;

  // Wh slice -> smem: ws[(kq*JPC + j)*4 + kk] = Wh[j0+j][4kq+kk]
  {
    float4* ws4 = (float4*)ws;
    const float4* W4 = (const float4*)Wh;
    for (int i = tid; i < JPC * (DD/4); i += RTPB) {
      int j = i / (DD/4), kq = i % (DD/4);
      ws4[kq * JPC + j] = W4[(size_t)(j0 + j) * (DD/4) + kq];
    }
  }

  // epilogue task mapping: task = b*JPC + jj (320 tasks over 256 threads)
  const int b1 = tid / JPC, jj1 = tid % JPC;
  const int o1  = b1 * DD + j0 + jj1;
  const int ha1 = ((j0 + jj1) >> 2) * 128 + b1 * 4 + ((j0 + jj1) & 3);
  const bool has2 = (tid < JPC * BB - RTPB);
  const int task2 = tid + RTPB;
  const int b2 = task2 / JPC, jj2 = task2 % JPC;
  const int o2  = b2 * DD + j0 + jj2;
  const int ha2 = ((j0 + jj2) >> 2) * 128 + b2 * 4 + ((j0 + jj2) & 3);

  __syncthreads();

  const int kq0 = wid * QSPAN;
  const unsigned* myflag = g_flag + wid * 16 + (lane & 15);  // this warp's 16 producers

  size_t base = 0;
  float xp1 = __ldcs(&g_xp[o1]);
  float z1  = __ldcs(&zseq[o1]);
  float xp2 = has2 ? __ldcs(&g_xp[o2]) : 0.f;
  float z2  = has2 ? __ldcs(&zseq[o2]) : 0.f;

  for (int t = 0; t < TT; ++t) {
    const float* hc = g_h[t & 1];
    float*       hn = g_h[(t & 1) ^ 1];
    float sz1 = z1 / (1.0f + __expf(-z1));
    float sz2 = has2 ? (z2 / (1.0f + __expf(-z2))) : 0.f;

    // ---- per-warp dataflow wait: my 16 producers have written h_t ----
    if (t > 0) {
      while (true) {
        unsigned v = ld_acq(myflag);            // acquire in every lane
        if (__all_sync(0xffffffffu, v >= (unsigned)t)) break;
        __nanosleep(32);
      }
    }

    // ---- partial dot products: lane = batch, 10 columns, 160 k per warp ----
    ull acc[JPC];
    #pragma unroll
    for (int j = 0; j < JPC; ++j) acc[j] = 0ull;

    const char* hp = (const char*)(hc + (size_t)kq0 * 128 + lane * 4);
    ull h0r[4], h1r[4];
    #pragma unroll
    for (int d = 0; d < 4; ++d) ld_cg_v2u64(hp + (size_t)d * 512, h0r[d], h1r[d]);
    #pragma unroll 4
    for (int q = 0; q < QSPAN; ++q) {
      ull h0 = h0r[q & 3], h1 = h1r[q & 3];
      if (q + 4 < QSPAN) ld_cg_v2u64(hp + (size_t)(q + 4) * 512, h0r[q & 3], h1r[q & 3]);
      const ulonglong2* wq = (const ulonglong2*)(ws + (size_t)(kq0 + q) * (JPC * 4));
      #pragma unroll
      for (int j = 0; j < JPC; ++j) {
        ulonglong2 wv = wq[j];        // broadcast LDS.128
        ffma2(acc[j], h0, wv.x);
        ffma2(acc[j], h1, wv.y);
      }
    }

    // ---- stage partials: redb[wid][lane][j] ----
    {
      float s[JPC];
      #pragma unroll
      for (int j = 0; j < JPC; ++j) { float2 p = unpack2(acc[j]); s[j] = p.x + p.y; }
      float* rp = redb + wid * 384 + lane * 12;
      *(float4*)(rp + 0) = make_float4(s[0], s[1], s[2], s[3]);
      *(float4*)(rp + 4) = make_float4(s[4], s[5], s[6], s[7]);
      *(float2*)(rp + 8) = make_float2(s[8], s[9]);
    }
    __syncthreads();   // A: partials visible; also: all warps passed their flag polls
                       //    => safe to overwrite buffer hn (= h_{t-1}) below

    // ---- epilogue: reduce 8 partials, tanh, gate, store ----
    {
      float s = 0.f;
      #pragma unroll
      for (int w = 0; w < NW; ++w) s += redb[w * 384 + b1 * 12 + jj1];
      float h = tanhf(xp1 + s);
      out[base + o1] = h * sz1;
      st_cg_f32(&hn[ha1], h);
      if (t == TT - 1) hlast[o1] = h;
    }
    if (has2) {
      float s = 0.f;
      #pragma unroll
      for (int w = 0; w < NW; ++w) s += redb[w * 384 + b2 * 12 + jj2];
      float h = tanhf(xp2 + s);
      out[base + o2] = h * sz2;
      st_cg_f32(&hn[ha2], h);
      if (t == TT - 1) hlast[o2] = h;
    }
    __syncthreads();   // B: all hn stores + redb reads complete

    // ---- publish: h_{t+1} columns of this CTA are ready ----
    if (tid == 0) st_rel(&g_flag[bid], (unsigned)(t + 1));

    // prefetch next step's gate inputs (overlaps peers' flag latency)
    base += (size_t)BB * DD;
    if (t + 1 < TT) {
      xp1 = __ldcs(&g_xp[base + o1]);
      z1  = __ldcs(&zseq[base + o1]);
      if (has2) { xp2 = __ldcs(&g_xp[base + o2]); z2 = __ldcs(&zseq[base + o2]); }
    }
  }
}

// ======================================================================
extern "C" void kernel_launch(void* const* d_in, const int* in_sizes, int n_in,
                              void* d_out, int out_size)
{
  const float* x    = (const float*)d_in[0];   // [T,B,D]
  const float* z    = (const float*)d_in[1];   // [T,B,D]
  const float* h0   = (const float*)d_in[2];   // [B,D]
  const float* Wx   = (const float*)d_in[3];   // [D,D]
  const float* Wh   = (const float*)d_in[4];   // [D,D]
  const float* bias = (const float*)d_in[5];   // [D]

  float* out = (float*)d_out;
  void* dummy = nullptr;
  cudaGetSymbolAddress(&dummy, g_hlast_dummy);
  float* hlast = (out_size >= (int)(TBD + BB * DD)) ? (out + TBD) : (float*)dummy;

  const int rec_smem = (JPC * DD + NW * 384) * (int)sizeof(float);
  cudaFuncSetAttribute(recurrence, cudaFuncAttributeMaxDynamicSharedMemorySize, rec_smem);

  init_state<<<40, 256>>>(h0);
  gemm_xproj<<<dim3(128, 10), 256>>>(x, Wx, bias);
  recurrence<<<RNC, RTPB, rec_smem>>>(z, Wh, out, hlast);
}